// round 5
// baseline (speedup 1.0000x reference)
#include <cuda_runtime.h>
#include <cuda_fp16.h>
#include <cstdint>
#include <math.h>

#define BB 512
#define RR 1152
#define OO 16
#define CO 160
#define II 8

// u_hat fp16 [b][r][co], 189 MB; iter0 partials; v vectors
__device__ uint4 g_uhat4[(size_t)BB * RR * CO / 8];
__device__ float g_part[18 * BB * CO];   // [rtile][b][co]
__device__ float g_v0[BB * CO];
__device__ float g_vsum[BB * CO];

// ---- packed f32x2 helpers (sm_103a FFMA2 path, PTX-only) --------------------
__device__ __forceinline__ unsigned long long pk2(float a, float b) {
    unsigned long long v;
    asm("mov.b64 %0, {%1, %2};" : "=l"(v) : "f"(a), "f"(b));
    return v;
}
__device__ __forceinline__ float2 unpk2(unsigned long long v) {
    float2 r;
    asm("mov.b64 {%0, %1}, %2;" : "=f"(r.x), "=f"(r.y) : "l"(v));
    return r;
}
__device__ __forceinline__ unsigned long long fma2(unsigned long long a,
                                                   unsigned long long b,
                                                   unsigned long long c) {
    unsigned long long d;
    asm("fma.rn.f32x2 %0, %1, %2, %3;" : "=l"(d) : "l"(a), "l"(b), "l"(c));
    return d;
}
__device__ __forceinline__ unsigned long long add2(unsigned long long a,
                                                   unsigned long long b) {
    unsigned long long d;
    asm("add.rn.f32x2 %0, %1, %2;" : "=l"(d) : "l"(a), "l"(b));
    return d;
}

// ---------------------------------------------------------------------------
// K1': fused einsum + iter0 partial sum.
// Grid (btile 8 x rtile 18): block owns 64 b x 64 r. 320 threads:
//   oc = t%20 (co-octet: co = oc*8..+8, i.e. 4 co-pairs), bg = t/20 (4 b's).
// W staged as f32x2 co-pairs, x staged duplicated (x,x) -> all math is
// packed fp32 (2 FMA/instr). u written fp16 uint4 (STG.128); block-local
// fp32 sum over its 64 r's written to g_part[rtile].
// ---------------------------------------------------------------------------
#define BT 64
#define RT 64
#define RB 4

__global__ __launch_bounds__(320) void uhat_s0_kernel(const float* __restrict__ x,
                                                      const float* __restrict__ W) {
    const int tid = threadIdx.x;
    const int oc = tid % 20;
    const int bg = tid / 20;
    const int b0 = blockIdx.x * BT;
    const int r0 = blockIdx.y * RT;

    __shared__ unsigned long long wst[RB * 640];  // [rl][pair(80)][i(8)] f32x2, 20KB
    __shared__ unsigned long long xst[RB * 512];  // [rl][b(64)][i(8)]    (x,x), 16KB

    unsigned long long acc2[4][4];
#pragma unroll
    for (int bb = 0; bb < 4; bb++)
#pragma unroll
        for (int pp = 0; pp < 4; pp++) acc2[bb][pp] = 0ull;

    for (int rblk = 0; rblk < RT / RB; rblk++) {
        const int rbase = r0 + rblk * RB;

        // stage W pairs: wst[rl*640 + p*8 + i] = (W[r][2p][i], W[r][2p+1][i])
        for (int idx = tid; idx < RB * 640; idx += 320) {
            int rl = idx / 640, rem = idx % 640;
            int p = rem >> 3, i = rem & 7;
            const float* wr = W + (size_t)(rbase + rl) * (CO * II);
            wst[idx] = pk2(wr[(2 * p) * II + i], wr[(2 * p + 1) * II + i]);
        }
        // stage x duplicated: xst[rl*512 + b*8 + i] = (x_i, x_i)
        for (int idx = tid; idx < RB * 512; idx += 320) {
            int rl = idx / 512, rem = idx % 512;
            int bl = rem >> 3, i = rem & 7;
            float v = x[(size_t)(b0 + bl) * (RR * II) + (size_t)(rbase + rl) * II + i];
            xst[idx] = pk2(v, v);
        }
        __syncthreads();

#pragma unroll
        for (int rl = 0; rl < RB; rl++) {
            const int r = rbase + rl;
            const unsigned long long* wp = wst + rl * 640 + oc * 32;  // 4 pairs x 8
            unsigned long long wr[32];
#pragma unroll
            for (int k = 0; k < 32; k++) wr[k] = wp[k];

#pragma unroll
            for (int bb = 0; bb < 4; bb++) {
                const int b = b0 + bg * 4 + bb;
                const unsigned long long* xp = xst + rl * 512 + (bg * 4 + bb) * 8;
                unsigned long long xr[8];
#pragma unroll
                for (int i = 0; i < 8; i++) xr[i] = xp[i];

                unsigned int h[4];
#pragma unroll
                for (int pp = 0; pp < 4; pp++) {
                    unsigned long long u2 = 0ull;
#pragma unroll
                    for (int i = 0; i < 8; i++) u2 = fma2(wr[pp * 8 + i], xr[i], u2);
                    acc2[bb][pp] = add2(acc2[bb][pp], u2);
                    float2 uf = unpk2(u2);
                    __half2 hv = __floats2half2_rn(uf.x, uf.y);
                    h[pp] = *reinterpret_cast<unsigned int*>(&hv);
                }
                uint4 out;
                out.x = h[0]; out.y = h[1]; out.z = h[2]; out.w = h[3];
                g_uhat4[((size_t)b * RR + r) * (CO / 8) + oc] = out;
            }
        }
        __syncthreads();
    }

    // write iter0 partial: g_part[(rtile*BB + b)*CO + oc*8 .. +8]
#pragma unroll
    for (int bb = 0; bb < 4; bb++) {
        const int b = b0 + bg * 4 + bb;
        float2 p0 = unpk2(acc2[bb][0]), p1 = unpk2(acc2[bb][1]);
        float2 p2 = unpk2(acc2[bb][2]), p3 = unpk2(acc2[bb][3]);
        float4* dst = reinterpret_cast<float4*>(
            g_part + ((size_t)blockIdx.y * BB + b) * CO + oc * 8);
        dst[0] = make_float4(p0.x, p0.y, p1.x, p1.y);
        dst[1] = make_float4(p2.x, p2.y, p3.x, p3.y);
    }
}

// ---------------------------------------------------------------------------
// K0b: v0 = squash(0.1 * sum_rt part + bias). Grid 512, 160 threads.
// ---------------------------------------------------------------------------
__global__ __launch_bounds__(160) void v0_kernel(const float* __restrict__ bias) {
    const int b = blockIdx.x;
    const int tid = threadIdx.x;
    __shared__ float s_sm[CO];

    float s = 0.0f;
#pragma unroll
    for (int rt = 0; rt < 18; rt++) s += g_part[((size_t)rt * BB + b) * CO + tid];
    s = 0.1f * s + bias[tid];
    s_sm[tid] = s;
    __syncthreads();

    int c = tid >> 4;
    float nsq = 0.0f;
#pragma unroll
    for (int o = 0; o < OO; o++) {
        float t = s_sm[c * 16 + o];
        nsq += t * t;
    }
    g_v0[b * CO + tid] = s_sm[tid] * (sqrtf(nsq) / (1.0f + nsq + 1e-8f));
}

// ---------------------------------------------------------------------------
// Routing pass (verbatim R2 logic, modes 1/2 only). Block per b, 8 warps,
// warp handles 8-row chunks; lane task t=l+32j: row=t/20, q=t%20 (q=2c+half).
//   MODE 1: logits = u.v0     -> writes vsum = v0 + v1
//   MODE 2: logits = u.vsum   -> writes v2 -> dout
// ---------------------------------------------------------------------------
#define CHUNK 8
#define NCHUNK (RR / CHUNK)

template <int MODE>
__global__ __launch_bounds__(256) void route_kernel(const float* __restrict__ bias,
                                                    float* __restrict__ dout) {
    const int b = blockIdx.x;
    const int tid = threadIdx.x;
    const int w = tid >> 5;
    const int l = tid & 31;

    __shared__ float part[8][CHUNK][CO];
    __shared__ float e_sm[8][80];
    __shared__ float inv_sm[8][8];
    __shared__ float v_sm[CO];

    const float* vin = (MODE == 1) ? g_v0 : g_vsum;
    if (tid < CO) v_sm[tid] = vin[b * CO + tid];
    __syncthreads();

    int rowj[5], qj[5];
    __half2 v2[5][4];
#pragma unroll
    for (int j = 0; j < 5; j++) {
        int t = l + 32 * j;
        rowj[j] = t / 20;
        qj[j] = t % 20;
        const float* vq = v_sm + qj[j] * 8;
#pragma unroll
        for (int k = 0; k < 4; k++)
            v2[j][k] = __floats2half2_rn(vq[2 * k], vq[2 * k + 1]);
    }

    float acc[5][8];
#pragma unroll
    for (int j = 0; j < 5; j++)
#pragma unroll
        for (int k = 0; k < 8; k++) acc[j][k] = 0.0f;

    const uint4* ubase = g_uhat4 + (size_t)b * RR * (CO / 8);

    for (int ch = w; ch < NCHUNK; ch += 8) {
        const uint4* p = ubase + ch * (CHUNK * CO / 8);
        uint4 uu[5];
#pragma unroll
        for (int j = 0; j < 5; j++) uu[j] = p[l + 32 * j];

        float e[5];
#pragma unroll
        for (int j = 0; j < 5; j++) {
            const __half2* u2 = reinterpret_cast<const __half2*>(&uu[j]);
            __half2 p2 = __hmul2(u2[0], v2[j][0]);
            p2 = __hfma2(u2[1], v2[j][1], p2);
            p2 = __hfma2(u2[2], v2[j][2], p2);
            p2 = __hfma2(u2[3], v2[j][3], p2);
            unsigned int pu = __shfl_xor_sync(0xffffffffu, *reinterpret_cast<unsigned int*>(&p2), 1);
            p2 = __hadd2(p2, *reinterpret_cast<__half2*>(&pu));
            float lg = __low2float(p2) + __high2float(p2);
            e[j] = __expf(lg);  // logits bounded; no max-sub needed
        }
        if (!(l & 1)) {
#pragma unroll
            for (int j = 0; j < 5; j++) e_sm[w][(l >> 1) + 16 * j] = e[j];
        }
        __syncwarp();
        if (l < 8) {
            float s = 0.0f;
#pragma unroll
            for (int i = 0; i < 10; i++) s += e_sm[w][l * 10 + i];
            inv_sm[w][l] = 1.0f / s;
        }
        __syncwarp();

#pragma unroll
        for (int j = 0; j < 5; j++) {
            float wgt = e[j] * inv_sm[w][rowj[j]];
            const __half2* u2 = reinterpret_cast<const __half2*>(&uu[j]);
#pragma unroll
            for (int k = 0; k < 4; k++) {
                float2 uf = __half22float2(u2[k]);
                acc[j][2 * k] += wgt * uf.x;
                acc[j][2 * k + 1] += wgt * uf.y;
            }
        }
    }

#pragma unroll
    for (int j = 0; j < 5; j++)
#pragma unroll
        for (int k = 0; k < 8; k++) part[w][rowj[j]][qj[j] * 8 + k] = acc[j][k];
    __syncthreads();

    if (tid < CO) {
        float s = 0.0f;
#pragma unroll
        for (int i = 0; i < 64; i++) s += (&part[0][0][0])[i * CO + tid];
        s += bias[tid];
        part[0][0][tid] = s;
    }
    __syncthreads();

    if (tid < CO) {
        int c = tid >> 4;
        float nsq = 0.0f;
#pragma unroll
        for (int o = 0; o < OO; o++) {
            float t = part[0][0][c * OO + o];
            nsq += t * t;
        }
        float val = part[0][0][tid] * (sqrtf(nsq) / (1.0f + nsq + 1e-8f));
        if (MODE == 1) g_vsum[b * CO + tid] = v_sm[tid] + val;  // v0 + v1
        else dout[b * CO + tid] = val;                          // v2
    }
}

// ---------------------------------------------------------------------------
extern "C" void kernel_launch(void* const* d_in, const int* in_sizes, int n_in,
                              void* d_out, int out_size) {
    const float* x    = (const float*)d_in[0];  // [512,1152,8]
    const float* W    = (const float*)d_in[1];  // [1152,10,16,8]
    const float* bias = (const float*)d_in[2];  // [1,1,10,16]
    float* out = (float*)d_out;                 // [512,10,16]

    uhat_s0_kernel<<<dim3(BB / BT, RR / RT), 320>>>(x, W);
    v0_kernel<<<BB, 160>>>(bias);
    route_kernel<1><<<BB, 256>>>(bias, out);
    route_kernel<2><<<BB, 256>>>(bias, out);
}

// round 6
// speedup vs baseline: 1.9402x; 1.9402x over previous
#include <cuda_runtime.h>
#include <cuda_fp16.h>
#include <cstdint>
#include <math.h>

#define BB 512
#define RR 1152
#define OO 16
#define CO 160
#define II 8
#define CHUNK 8
#define NCHUNK (RR / CHUNK)  // 144
#define ITERS (NCHUNK / 8)   // 18 chunk-iterations per warp

// u_hat fp16 [b][r][co], 189 MB; v vectors (sanctioned __device__ scratch)
__device__ uint4 g_uhat4[(size_t)BB * RR * CO / 8];
__device__ float g_v0[BB * CO];
__device__ float g_vsum[BB * CO];

// ---- packed f32x2 helpers (sm_103a FFMA2, PTX-only) -------------------------
__device__ __forceinline__ unsigned long long pk2(float a, float b) {
    unsigned long long v;
    asm("mov.b64 %0, {%1, %2};" : "=l"(v) : "f"(a), "f"(b));
    return v;
}
__device__ __forceinline__ float2 unpk2(unsigned long long v) {
    float2 r;
    asm("mov.b64 {%0, %1}, %2;" : "=f"(r.x), "=f"(r.y) : "l"(v));
    return r;
}
__device__ __forceinline__ unsigned long long fma2(unsigned long long a,
                                                   unsigned long long b,
                                                   unsigned long long c) {
    unsigned long long d;
    asm("fma.rn.f32x2 %0, %1, %2, %3;" : "=l"(d) : "l"(a), "l"(b), "l"(c));
    return d;
}

// ---------------------------------------------------------------------------
// K1: u_hat fp16 [b][r][co]. Block per r (proven R2 layout), packed f32x2 math.
// Lane owns co-pairs p = s*32+l (s=0,1; s=2 only l<16). Stores are half2
// (co 2p, 2p+1) -> contiguous 128B per warp slot.
// ---------------------------------------------------------------------------
__global__ __launch_bounds__(256) void uhat_kernel(const float* __restrict__ x,
                                                   const float* __restrict__ W) {
    const int r = blockIdx.x;
    const int tid = threadIdx.x;
    const int w = tid >> 5;
    const int l = tid & 31;

    __shared__ float4 xs4[BB * 2];  // 16 KB: x[:, r, :]

    for (int idx = tid; idx < BB * 2; idx += 256)
        xs4[idx] = reinterpret_cast<const float4*>(x)[(size_t)(idx >> 1) * (RR * 2) + r * 2 + (idx & 1)];

    // W packed: wp[s][i] = (W[r][2p][i], W[r][2p+1][i])
    const float* Wr = W + (size_t)r * CO * II;
    unsigned long long wp[3][8];
#pragma unroll
    for (int s = 0; s < 3; s++) {
        if (s < 2 || l < 16) {
            int p = s * 32 + l;
            const float4* A = reinterpret_cast<const float4*>(Wr + (2 * p) * II);
            const float4* B = reinterpret_cast<const float4*>(Wr + (2 * p + 1) * II);
            float4 a0 = A[0], a1 = A[1], b0 = B[0], b1 = B[1];
            wp[s][0] = pk2(a0.x, b0.x); wp[s][1] = pk2(a0.y, b0.y);
            wp[s][2] = pk2(a0.z, b0.z); wp[s][3] = pk2(a0.w, b0.w);
            wp[s][4] = pk2(a1.x, b1.x); wp[s][5] = pk2(a1.y, b1.y);
            wp[s][6] = pk2(a1.z, b1.z); wp[s][7] = pk2(a1.w, b1.w);
        }
    }
    __syncthreads();

    for (int b = w; b < BB; b += 8) {
        const float4 xa = xs4[b * 2 + 0];
        const float4 xb = xs4[b * 2 + 1];
        unsigned long long xp[8];
        xp[0] = pk2(xa.x, xa.x); xp[1] = pk2(xa.y, xa.y);
        xp[2] = pk2(xa.z, xa.z); xp[3] = pk2(xa.w, xa.w);
        xp[4] = pk2(xb.x, xb.x); xp[5] = pk2(xb.y, xb.y);
        xp[6] = pk2(xb.z, xb.z); xp[7] = pk2(xb.w, xb.w);
        __half2* outp = reinterpret_cast<__half2*>(g_uhat4 + ((size_t)b * RR + r) * (CO / 8));
#pragma unroll
        for (int s = 0; s < 3; s++) {
            if (s < 2 || l < 16) {
                unsigned long long u2 = 0ull;
#pragma unroll
                for (int i = 0; i < 8; i++) u2 = fma2(wp[s][i], xp[i], u2);
                float2 uf = unpk2(u2);
                outp[s * 32 + l] = __floats2half2_rn(uf.x, uf.y);
            }
        }
    }
}

// ---------------------------------------------------------------------------
// Routing pass (R2 logic + prefetch pipelining). Block per b, 8 warps,
// lane task t=l+32j: row=t/20, q=t%20 (q=2c+half, o in [8*(q&1), +8)).
//   MODE 0: c uniform (=0.1) -> g_v0
//   MODE 1: logits = u.v0    -> g_vsum = v0 + v1
//   MODE 2: logits = u.vsum  -> v2 -> dout
// v held in smem as half2 pairs; re-read per chunk via opaque asm LDS
// (keeps regs low so 2 CTAs/SM survive the prefetch buffer).
// ---------------------------------------------------------------------------
template <int MODE>
__global__ __launch_bounds__(256) void route_kernel(const float* __restrict__ bias,
                                                    float* __restrict__ dout) {
    const int b = blockIdx.x;
    const int tid = threadIdx.x;
    const int w = tid >> 5;
    const int l = tid & 31;

    __shared__ float part[8][CHUNK][CO];  // 40 KB
    __shared__ float e_sm[8][80];
    __shared__ float inv_sm[8][8];
    __shared__ float v_sm[CO];
    __shared__ unsigned int vh[80];       // v as half2 pairs (co 2t, 2t+1)

    if (MODE > 0) {
        const float* vin = (MODE == 1) ? g_v0 : g_vsum;
        if (tid < CO) v_sm[tid] = vin[b * CO + tid];
        __syncthreads();
        if (tid < 80) {
            __half2 hv = __floats2half2_rn(v_sm[2 * tid], v_sm[2 * tid + 1]);
            vh[tid] = *reinterpret_cast<unsigned int*>(&hv);
        }
    }
    __syncthreads();

    int rowj[5], qj[5];
    unsigned int vaddr[5];
#pragma unroll
    for (int j = 0; j < 5; j++) {
        int t = l + 32 * j;
        rowj[j] = t / 20;
        qj[j] = t % 20;
        vaddr[j] = (unsigned int)__cvta_generic_to_shared(&vh[qj[j] * 4]);
    }

    float acc[5][8];
#pragma unroll
    for (int j = 0; j < 5; j++)
#pragma unroll
        for (int k = 0; k < 8; k++) acc[j][k] = 0.0f;

    const uint4* ubase = g_uhat4 + (size_t)b * RR * (CO / 8);

    // prefetch chunk 0
    uint4 cur[5];
    {
        const uint4* p = ubase + w * (CHUNK * CO / 8);
#pragma unroll
        for (int j = 0; j < 5; j++) cur[j] = p[l + 32 * j];
    }

    for (int it = 0; it < ITERS; it++) {
        uint4 nxt[5];
        if (it < ITERS - 1) {
            const uint4* pn = ubase + (w + (it + 1) * 8) * (CHUNK * CO / 8);
#pragma unroll
            for (int j = 0; j < 5; j++) nxt[j] = pn[l + 32 * j];
        }

        float wgt[5];
        if (MODE > 0) {
            float e[5];
#pragma unroll
            for (int j = 0; j < 5; j++) {
                unsigned int v0r, v1r, v2r, v3r;
                asm volatile("ld.shared.v2.b32 {%0,%1},[%2];"
                             : "=r"(v0r), "=r"(v1r) : "r"(vaddr[j]));
                asm volatile("ld.shared.v2.b32 {%0,%1},[%2];"
                             : "=r"(v2r), "=r"(v3r) : "r"(vaddr[j] + 8));
                const __half2* u2 = reinterpret_cast<const __half2*>(&cur[j]);
                __half2 p2 = __hmul2(u2[0], *reinterpret_cast<__half2*>(&v0r));
                p2 = __hfma2(u2[1], *reinterpret_cast<__half2*>(&v1r), p2);
                p2 = __hfma2(u2[2], *reinterpret_cast<__half2*>(&v2r), p2);
                p2 = __hfma2(u2[3], *reinterpret_cast<__half2*>(&v3r), p2);
                unsigned int pu = __shfl_xor_sync(0xffffffffu, *reinterpret_cast<unsigned int*>(&p2), 1);
                p2 = __hadd2(p2, *reinterpret_cast<__half2*>(&pu));
                float lg = __low2float(p2) + __high2float(p2);
                e[j] = __expf(lg);  // logits bounded; no max-sub needed
            }
            if (!(l & 1)) {
#pragma unroll
                for (int j = 0; j < 5; j++) e_sm[w][(l >> 1) + 16 * j] = e[j];
            }
            __syncwarp();
            if (l < 8) {
                float s = 0.0f;
#pragma unroll
                for (int i = 0; i < 10; i++) s += e_sm[w][l * 10 + i];
                inv_sm[w][l] = 1.0f / s;
            }
            __syncwarp();
#pragma unroll
            for (int j = 0; j < 5; j++) wgt[j] = e[j] * inv_sm[w][rowj[j]];
        }

#pragma unroll
        for (int j = 0; j < 5; j++) {
            const __half2* u2 = reinterpret_cast<const __half2*>(&cur[j]);
#pragma unroll
            for (int k = 0; k < 4; k++) {
                float2 uf = __half22float2(u2[k]);
                if (MODE == 0) {
                    acc[j][2 * k] += uf.x;
                    acc[j][2 * k + 1] += uf.y;
                } else {
                    acc[j][2 * k] += wgt[j] * uf.x;
                    acc[j][2 * k + 1] += wgt[j] * uf.y;
                }
            }
        }

        if (it < ITERS - 1) {
#pragma unroll
            for (int j = 0; j < 5; j++) cur[j] = nxt[j];
        }
    }

#pragma unroll
    for (int j = 0; j < 5; j++)
#pragma unroll
        for (int k = 0; k < 8; k++) part[w][rowj[j]][qj[j] * 8 + k] = acc[j][k];
    __syncthreads();

    if (tid < CO) {
        float s = 0.0f;
#pragma unroll
        for (int i = 0; i < 64; i++) s += (&part[0][0][0])[i * CO + tid];
        if (MODE == 0) s *= 0.1f;  // softmax(0) = 1/10 exactly
        s += bias[tid];
        part[0][0][tid] = s;
    }
    __syncthreads();

    if (tid < CO) {
        int c = tid >> 4;
        float nsq = 0.0f;
#pragma unroll
        for (int o = 0; o < OO; o++) {
            float t = part[0][0][c * OO + o];
            nsq += t * t;
        }
        float val = part[0][0][tid] * (sqrtf(nsq) / (1.0f + nsq + 1e-8f));
        if (MODE == 0) g_v0[b * CO + tid] = val;
        else if (MODE == 1) g_vsum[b * CO + tid] = v_sm[tid] + val;  // v0+v1
        else dout[b * CO + tid] = val;
    }
}

// ---------------------------------------------------------------------------
extern "C" void kernel_launch(void* const* d_in, const int* in_sizes, int n_in,
                              void* d_out, int out_size) {
    const float* x    = (const float*)d_in[0];  // [512,1152,8]
    const float* W    = (const float*)d_in[1];  // [1152,10,16,8]
    const float* bias = (const float*)d_in[2];  // [1,1,10,16]
    float* out = (float*)d_out;                 // [512,10,16]

    uhat_kernel<<<RR, 256>>>(x, W);
    route_kernel<0><<<BB, 256>>>(bias, out);
    route_kernel<1><<<BB, 256>>>(bias, out);
    route_kernel<2><<<BB, 256>>>(bias, out);
}

// round 7
// speedup vs baseline: 2.2084x; 1.1382x over previous
#include <cuda_runtime.h>
#include <cuda_fp16.h>
#include <cstdint>
#include <math.h>

#define BB 512
#define RR 1152
#define OO 16
#define CO 160
#define II 8
#define CHUNK 8
#define NCHUNK (RR / CHUNK)  // 144
#define ITERS (NCHUNK / 8)   // 18 chunk-iterations per warp

// u_hat fp16 [b][r][co], 189 MB (sanctioned __device__ scratch)
__device__ uint4 g_uhat4[(size_t)BB * RR * CO / 8];

// ---------------------------------------------------------------------------
// K1: u_hat fp16 [b][r][co]. Block per r; W register-resident; x staged in
// smem. Plain FFMA (proven R2 version — f32x2 variant regressed).
// Lane owns co-pairs p = s*32+l (s=0,1; s=2 only l<16); half2 stores.
// ---------------------------------------------------------------------------
__global__ __launch_bounds__(256) void uhat_kernel(const float* __restrict__ x,
                                                   const float* __restrict__ W) {
    const int r = blockIdx.x;
    const int tid = threadIdx.x;
    const int w = tid >> 5;
    const int l = tid & 31;

    __shared__ float4 xs4[BB * 2];  // 16 KB: x[:, r, :]

    for (int idx = tid; idx < BB * 2; idx += 256)
        xs4[idx] = reinterpret_cast<const float4*>(x)[(size_t)(idx >> 1) * (RR * 2) + r * 2 + (idx & 1)];

    const float4* W4 = reinterpret_cast<const float4*>(W + (size_t)r * CO * II);
    float4 wA[3][4];
#pragma unroll
    for (int s = 0; s < 3; s++) {
        if (s < 2 || l < 16) {
            int p = s * 32 + l;
#pragma unroll
            for (int q = 0; q < 4; q++) wA[s][q] = W4[p * 4 + q];
        }
    }
    __syncthreads();

    for (int b = w; b < BB; b += 8) {
        const float4 xa = xs4[b * 2 + 0];
        const float4 xb = xs4[b * 2 + 1];
        __half2* outp = reinterpret_cast<__half2*>(g_uhat4 + ((size_t)b * RR + r) * (CO / 8));
#pragma unroll
        for (int s = 0; s < 3; s++) {
            if (s < 2 || l < 16) {
                float u0 = wA[s][0].x * xa.x + wA[s][0].y * xa.y + wA[s][0].z * xa.z + wA[s][0].w * xa.w +
                           wA[s][1].x * xb.x + wA[s][1].y * xb.y + wA[s][1].z * xb.z + wA[s][1].w * xb.w;
                float u1 = wA[s][2].x * xa.x + wA[s][2].y * xa.y + wA[s][2].z * xa.z + wA[s][2].w * xa.w +
                           wA[s][3].x * xb.x + wA[s][3].y * xb.y + wA[s][3].z * xb.z + wA[s][3].w * xb.w;
                outp[s * 32 + l] = __floats2half2_rn(u0, u1);
            }
        }
    }
}

// ---------------------------------------------------------------------------
// Fused routing: block per b runs ALL 3 iterations, re-reading u_hat[b]
// (360 KB) from global each round — rounds 1-2 served mostly from L2
// (concurrent working set 2 CTA/SM x 148 SM x 360KB ~ 106 MB < 126 MB L2).
// All v state block-local in smem (no global v buffers, no extra launches).
// Lane task t=l+32j: row=t/20, q=t%20 (q=2c+half, o in [8*(q&1), +8)).
//   round 0: c uniform (=0.1) -> v0
//   round 1: logits = u.v0    -> vacc = v0 + v1
//   round 2: logits = u.vacc  -> v2 -> dout
// ---------------------------------------------------------------------------
__global__ __launch_bounds__(256) void route3_kernel(const float* __restrict__ bias,
                                                     float* __restrict__ dout) {
    const int b = blockIdx.x;
    const int tid = threadIdx.x;
    const int w = tid >> 5;
    const int l = tid & 31;

    __shared__ float part[8][CHUNK][CO];  // 40 KB
    __shared__ float e_sm[8][80];
    __shared__ float inv_sm[8][8];
    __shared__ float vacc[CO];            // v0, then v0+v1
    __shared__ unsigned int vh[80];       // current v as half2 pairs

    int rowj[5], qj[5];
    unsigned int vaddr[5];
#pragma unroll
    for (int j = 0; j < 5; j++) {
        int t = l + 32 * j;
        rowj[j] = t / 20;
        qj[j] = t % 20;
        vaddr[j] = (unsigned int)__cvta_generic_to_shared(&vh[qj[j] * 4]);
    }

    const uint4* ubase = g_uhat4 + (size_t)b * RR * (CO / 8);

    for (int round = 0; round < 3; round++) {
        float acc[5][8];
#pragma unroll
        for (int j = 0; j < 5; j++)
#pragma unroll
            for (int k = 0; k < 8; k++) acc[j][k] = 0.0f;

        // prefetch chunk 0
        uint4 cur[5];
        {
            const uint4* p = ubase + w * (CHUNK * CO / 8);
#pragma unroll
            for (int j = 0; j < 5; j++) cur[j] = p[l + 32 * j];
        }

        for (int it = 0; it < ITERS; it++) {
            uint4 nxt[5];
            if (it < ITERS - 1) {
                const uint4* pn = ubase + (w + (it + 1) * 8) * (CHUNK * CO / 8);
#pragma unroll
                for (int j = 0; j < 5; j++) nxt[j] = pn[l + 32 * j];
            }

            float wgt[5];
            if (round > 0) {
                float e[5];
#pragma unroll
                for (int j = 0; j < 5; j++) {
                    unsigned int v0r, v1r, v2r, v3r;
                    asm volatile("ld.shared.v2.b32 {%0,%1},[%2];"
                                 : "=r"(v0r), "=r"(v1r) : "r"(vaddr[j]));
                    asm volatile("ld.shared.v2.b32 {%0,%1},[%2];"
                                 : "=r"(v2r), "=r"(v3r) : "r"(vaddr[j] + 8));
                    const __half2* u2 = reinterpret_cast<const __half2*>(&cur[j]);
                    __half2 p2 = __hmul2(u2[0], *reinterpret_cast<__half2*>(&v0r));
                    p2 = __hfma2(u2[1], *reinterpret_cast<__half2*>(&v1r), p2);
                    p2 = __hfma2(u2[2], *reinterpret_cast<__half2*>(&v2r), p2);
                    p2 = __hfma2(u2[3], *reinterpret_cast<__half2*>(&v3r), p2);
                    unsigned int pu = __shfl_xor_sync(0xffffffffu, *reinterpret_cast<unsigned int*>(&p2), 1);
                    p2 = __hadd2(p2, *reinterpret_cast<__half2*>(&pu));
                    float lg = __low2float(p2) + __high2float(p2);
                    e[j] = __expf(lg);  // logits bounded; no max-sub needed
                }
                if (!(l & 1)) {
#pragma unroll
                    for (int j = 0; j < 5; j++) e_sm[w][(l >> 1) + 16 * j] = e[j];
                }
                __syncwarp();
                if (l < 8) {
                    float s = 0.0f;
#pragma unroll
                    for (int i = 0; i < 10; i++) s += e_sm[w][l * 10 + i];
                    inv_sm[w][l] = 1.0f / s;
                }
                __syncwarp();
#pragma unroll
                for (int j = 0; j < 5; j++) wgt[j] = e[j] * inv_sm[w][rowj[j]];
            }

#pragma unroll
            for (int j = 0; j < 5; j++) {
                const __half2* u2 = reinterpret_cast<const __half2*>(&cur[j]);
#pragma unroll
                for (int k = 0; k < 4; k++) {
                    float2 uf = __half22float2(u2[k]);
                    if (round == 0) {
                        acc[j][2 * k] += uf.x;
                        acc[j][2 * k + 1] += uf.y;
                    } else {
                        acc[j][2 * k] += wgt[j] * uf.x;
                        acc[j][2 * k + 1] += wgt[j] * uf.y;
                    }
                }
            }

            if (it < ITERS - 1) {
#pragma unroll
                for (int j = 0; j < 5; j++) cur[j] = nxt[j];
            }
        }

        // block reduce -> s -> squash -> new v (all in smem)
#pragma unroll
        for (int j = 0; j < 5; j++)
#pragma unroll
            for (int k = 0; k < 8; k++) part[w][rowj[j]][qj[j] * 8 + k] = acc[j][k];
        __syncthreads();

        if (tid < CO) {
            float s = 0.0f;
#pragma unroll
            for (int i = 0; i < 64; i++) s += (&part[0][0][0])[i * CO + tid];
            if (round == 0) s *= 0.1f;  // softmax(0) = 1/10 exactly
            s += bias[tid];
            part[0][0][tid] = s;
        }
        __syncthreads();

        if (tid < CO) {
            int c = tid >> 4;
            float nsq = 0.0f;
#pragma unroll
            for (int o = 0; o < OO; o++) {
                float t = part[0][0][c * OO + o];
                nsq += t * t;
            }
            float val = part[0][0][tid] * (sqrtf(nsq) / (1.0f + nsq + 1e-8f));
            if (round == 0) vacc[tid] = val;            // v0
            else if (round == 1) vacc[tid] += val;      // v0 + v1
            else dout[b * CO + tid] = val;              // v2 (final)
        }
        __syncthreads();

        if (round < 2 && tid < 80) {
            __half2 hv = __floats2half2_rn(vacc[2 * tid], vacc[2 * tid + 1]);
            vh[tid] = *reinterpret_cast<unsigned int*>(&hv);
        }
        __syncthreads();
    }
}

// ---------------------------------------------------------------------------
extern "C" void kernel_launch(void* const* d_in, const int* in_sizes, int n_in,
                              void* d_out, int out_size) {
    const float* x    = (const float*)d_in[0];  // [512,1152,8]
    const float* W    = (const float*)d_in[1];  // [1152,10,16,8]
    const float* bias = (const float*)d_in[2];  // [1,1,10,16]
    float* out = (float*)d_out;                 // [512,10,16]

    uhat_kernel<<<RR, 256>>>(x, W);
    route3_kernel<<<BB, 256>>>(bias, out);
}